// round 2
// baseline (speedup 1.0000x reference)
#include <cuda_runtime.h>
#include <cuda_bf16.h>

// dLDS_continuous: out[b] = expm(sum_m c[b,m] * G[m]) @ x[b]
// B = 2097152 batches, N = 3 (3x3 matrices), M = 6 basis operators.
//
// Algorithm per batch (all fp32, registers):
//   1. T = sum_m c[b,m] * G[m]              (G broadcast from shared)
//   2. s = max(0, ilogb-style exponent of ||T||_F)  -> ||T/2^s|| <= 1
//   3. E = Taylor_9(T / 2^s) via Horner      (8 3x3 matmuls)
//   4. E = E^(2^s)                           (s squarings, s typically 2, max ~4)
//   5. out = E @ x
//
// Error budget: Taylor-9 remainder at theta=1 is ~7e-7; squaring amplifies
// by ~2^s (<=32) -> ~2e-5 plus fp32 rounding. Well under the 1e-3 gate.

static constexpr int B_TOTAL = 2097152;
static constexpr int THREADS = 256;

__global__ void __launch_bounds__(THREADS)
expm_apply_kernel(const float* __restrict__ x,
                  const float* __restrict__ c,
                  const float* __restrict__ G,
                  float* __restrict__ out)
{
    __shared__ float sG[54];
    int tid = threadIdx.x;
    if (tid < 54) sG[tid] = G[tid];
    __syncthreads();

    int b = blockIdx.x * blockDim.x + tid;
    if (b >= B_TOTAL) return;

    // ---- load c[b, 0:6] as 3x float2 (24-byte stride keeps 8B alignment) ----
    const float2* c2 = reinterpret_cast<const float2*>(c) + (size_t)b * 3;
    float2 cv0 = c2[0];
    float2 cv1 = c2[1];
    float2 cv2 = c2[2];
    float cc[6] = {cv0.x, cv0.y, cv1.x, cv1.y, cv2.x, cv2.y};

    // ---- T = sum_m c[m] * G[m]  (row-major 3x3 in A[9]) ----
    float A[9];
#pragma unroll
    for (int k = 0; k < 9; ++k) {
        float s = cc[0] * sG[k];
#pragma unroll
        for (int m = 1; m < 6; ++m) s = fmaf(cc[m], sG[m * 9 + k], s);
        A[k] = s;
    }

    // ---- scaling: find s with ||A||_F / 2^s <= 1 ----
    float n2 = 0.f;
#pragma unroll
    for (int k = 0; k < 9; ++k) n2 = fmaf(A[k], A[k], n2);
    float nf = sqrtf(n2);

    // exponent e such that nf < 2^e (frexp convention: nf = m * 2^e, m in [0.5,1))
    int e = 0;
    frexpf(nf, &e);
    int s = e > 0 ? e : 0;
    if (s > 24) s = 24;  // safety clamp (unreachable for sane inputs)

    // exact power-of-two scale: 2^{-s}
    float sc = __int_as_float((127 - s) << 23);
#pragma unroll
    for (int k = 0; k < 9; ++k) A[k] *= sc;

    // ---- Taylor degree 9, Horner:  P = I + A/9; then P = I + (A*P)/k, k=8..1 ----
    float P[9];
#pragma unroll
    for (int k = 0; k < 9; ++k) P[k] = A[k] * (1.0f / 9.0f);
    P[0] += 1.f; P[4] += 1.f; P[8] += 1.f;

    const float rcp[8] = {1.f, 1.f / 2.f, 1.f / 3.f, 1.f / 4.f,
                          1.f / 5.f, 1.f / 6.f, 1.f / 7.f, 1.f / 8.f};
#pragma unroll
    for (int k = 8; k >= 1; --k) {
        float Q[9];
#pragma unroll
        for (int i = 0; i < 3; ++i) {
#pragma unroll
            for (int j = 0; j < 3; ++j) {
                Q[i * 3 + j] = fmaf(A[i * 3 + 0], P[0 + j],
                               fmaf(A[i * 3 + 1], P[3 + j],
                                    A[i * 3 + 2] * P[6 + j]));
            }
        }
        float r = rcp[k - 1];
#pragma unroll
        for (int t = 0; t < 9; ++t) P[t] = Q[t] * r;
        P[0] += 1.f; P[4] += 1.f; P[8] += 1.f;
    }

    // ---- repeated squaring: P <- P^2, s times ----
    for (int it = 0; it < s; ++it) {
        float Q[9];
#pragma unroll
        for (int i = 0; i < 3; ++i) {
#pragma unroll
            for (int j = 0; j < 3; ++j) {
                Q[i * 3 + j] = fmaf(P[i * 3 + 0], P[0 + j],
                               fmaf(P[i * 3 + 1], P[3 + j],
                                    P[i * 3 + 2] * P[6 + j]));
            }
        }
#pragma unroll
        for (int t = 0; t < 9; ++t) P[t] = Q[t];
    }

    // ---- out = P @ x ----
    const float* xb = x + (size_t)b * 3;
    float x0 = xb[0], x1 = xb[1], x2 = xb[2];
    float* ob = out + (size_t)b * 3;
    ob[0] = fmaf(P[0], x0, fmaf(P[1], x1, P[2] * x2));
    ob[1] = fmaf(P[3], x0, fmaf(P[4], x1, P[5] * x2));
    ob[2] = fmaf(P[6], x0, fmaf(P[7], x1, P[8] * x2));
}

extern "C" void kernel_launch(void* const* d_in, const int* in_sizes, int n_in,
                              void* d_out, int out_size)
{
    const float* x = (const float*)d_in[0];   // (B, 3, 1)
    const float* c = (const float*)d_in[1];   // (B, 6)
    const float* G = (const float*)d_in[2];   // (6, 3, 3)
    float* out = (float*)d_out;               // (B, 3, 1)

    int grid = (B_TOTAL + THREADS - 1) / THREADS;
    expm_apply_kernel<<<grid, THREADS>>>(x, c, G, out);
}

// round 3
// speedup vs baseline: 1.5588x; 1.5588x over previous
#include <cuda_runtime.h>
#include <cuda_bf16.h>

// dLDS_continuous: out[b] = expm(sum_m c[b,m] * G[m]) @ x[b]
// B = 2097152, N = 3, M = 6.
//
// Cayley-Hamilton formulation: for 3x3 A, every A^k = p0*I + p1*A + p2*A^2.
// 1. T = sum_m c[b,m] G[m];  A = T / 2^s with ||A||_F <= 1.
// 2. Invariants of A: I1=tr, I2=sum principal minors, I3=det.
//    A^3 = c0*I + c1*A + c2*A^2 with c0=I3, c1=-I2, c2=I1.
// 3. exp(A) ~= alpha0*I + alpha1*A + alpha2*A^2 via degree-9 Taylor where the
//    power recurrence runs on (p0,p1,p2) triples (3 FMA/step).
// 4. exp(T) = exp(A)^(2^s): squaring in coefficient space —
//    E^2 is a deg-4 poly in A, reduced via A^3, A^4 triples (~16 ops each).
// 5. out = a0*x + a1*(A x) + a2*(A(Ax)); A-matvecs use T with 2^-s folded in.
// Exact-arithmetic-identical to matrix Taylor+squaring; same error budget.

static constexpr int B_TOTAL = 2097152;
static constexpr int THREADS = 256;

__global__ void __launch_bounds__(THREADS)
expm_apply_kernel(const float* __restrict__ x,
                  const float* __restrict__ c,
                  const float* __restrict__ G,
                  float* __restrict__ out)
{
    __shared__ float sG[54];
    int tid = threadIdx.x;
    if (tid < 54) sG[tid] = G[tid];
    __syncthreads();

    int b = blockIdx.x * blockDim.x + tid;
    if (b >= B_TOTAL) return;

    // ---- c[b, 0:6] via 3x float2 ----
    const float2* c2 = reinterpret_cast<const float2*>(c) + (size_t)b * 3;
    float2 cv0 = c2[0];
    float2 cv1 = c2[1];
    float2 cv2 = c2[2];
    float cc[6] = {cv0.x, cv0.y, cv1.x, cv1.y, cv2.x, cv2.y};

    // ---- T = sum_m c[m] * G[m]  (row-major 3x3) ----
    float A[9];
#pragma unroll
    for (int k = 0; k < 9; ++k) {
        float s = cc[0] * sG[k];
#pragma unroll
        for (int m = 1; m < 6; ++m) s = fmaf(cc[m], sG[m * 9 + k], s);
        A[k] = s;
    }

    // ---- invariants of T ----
    float I1 = A[0] + A[4] + A[8];
    float m0 = fmaf(A[4], A[8], -A[5] * A[7]);   // minor of a00
    float m1 = fmaf(A[0], A[8], -A[2] * A[6]);   // minor of a11
    float m2 = fmaf(A[0], A[4], -A[1] * A[3]);   // minor of a22
    float I2 = m0 + m1 + m2;
    float u1 = fmaf(A[3], A[8], -A[5] * A[6]);
    float u2 = fmaf(A[3], A[7], -A[4] * A[6]);
    float I3 = fmaf(A[0], m0, fmaf(-A[1], u1, A[2] * u2));

    // ---- scaling exponent: ||T||_F <= 2^s ----
    float n2 = 0.f;
#pragma unroll
    for (int k = 0; k < 9; ++k) n2 = fmaf(A[k], A[k], n2);
    float nf = sqrtf(n2);
    int e = (__float_as_int(nf) >> 23) - 126;    // frexp-style exponent
    int s = e > 0 ? e : 0;
    if (s > 24) s = 24;
    float sc  = __int_as_float((127 - s) << 23); // 2^-s exact
    float sc2 = sc * sc;

    // scaled invariants: char poly of As = T*2^-s :  As^3 = c0 I + c1 As + c2 As^2
    float c2i = I1 * sc;
    float c1i = -I2 * sc2;
    float c0i = I3 * sc2 * sc;

    // ---- Taylor degree 9 in coefficient space ----
    // k=0,1,2 seed: alpha = (1, 1, 1/2), power triple p = repr(As^2) = (0,0,1)
    float a0 = 1.f, a1 = 1.f, a2 = 0.5f;
    float p0 = 0.f, p1 = 0.f, p2 = 1.f;
    float t = 0.5f;
    const float rk[7] = {1.f / 3.f, 1.f / 4.f, 1.f / 5.f, 1.f / 6.f,
                         1.f / 7.f, 1.f / 8.f, 1.f / 9.f};
#pragma unroll
    for (int k = 0; k < 7; ++k) {
        float np0 = p2 * c0i;
        float np1 = fmaf(p2, c1i, p0);
        float np2 = fmaf(p2, c2i, p1);
        t *= rk[k];
        a0 = fmaf(t, np0, a0);
        a1 = fmaf(t, np1, a1);
        a2 = fmaf(t, np2, a2);
        p0 = np0; p1 = np1; p2 = np2;
    }

    // ---- A^4 reduction triple: As^4 = d0 I + d1 As + d2 As^2 ----
    float d0 = c2i * c0i;
    float d1 = fmaf(c2i, c1i, c0i);
    float d2 = fmaf(c2i, c2i, c1i);

    // ---- s squarings in coefficient space ----
    for (int it = 0; it < s; ++it) {
        float q01 = a0 * a1;
        float q02 = a0 * a2;
        float q12 = a1 * a2;
        float q22 = a2 * a2;
        float t12 = q12 + q12;
        float b0 = fmaf(q22, d0, fmaf(t12, c0i, a0 * a0));
        float b1 = fmaf(q22, d1, fmaf(t12, c1i, q01 + q01));
        float b2 = fmaf(q22, d2, fmaf(t12, c2i, fmaf(a1, a1, q02 + q02)));
        a0 = b0; a1 = b1; a2 = b2;
    }

    // ---- out = a0*x + a1*(As x) + a2*(As^2 x),  As = T * 2^-s ----
    const float* xb = x + (size_t)b * 3;
    float x0 = xb[0], x1 = xb[1], x2 = xb[2];

    float y0 = sc * fmaf(A[0], x0, fmaf(A[1], x1, A[2] * x2));
    float y1 = sc * fmaf(A[3], x0, fmaf(A[4], x1, A[5] * x2));
    float y2 = sc * fmaf(A[6], x0, fmaf(A[7], x1, A[8] * x2));

    float z0 = sc * fmaf(A[0], y0, fmaf(A[1], y1, A[2] * y2));
    float z1 = sc * fmaf(A[3], y0, fmaf(A[4], y1, A[5] * y2));
    float z2 = sc * fmaf(A[6], y0, fmaf(A[7], y1, A[8] * y2));

    float* ob = out + (size_t)b * 3;
    ob[0] = fmaf(a0, x0, fmaf(a1, y0, a2 * z0));
    ob[1] = fmaf(a0, x1, fmaf(a1, y1, a2 * z1));
    ob[2] = fmaf(a0, x2, fmaf(a1, y2, a2 * z2));
}

extern "C" void kernel_launch(void* const* d_in, const int* in_sizes, int n_in,
                              void* d_out, int out_size)
{
    const float* x = (const float*)d_in[0];   // (B, 3, 1)
    const float* c = (const float*)d_in[1];   // (B, 6)
    const float* G = (const float*)d_in[2];   // (6, 3, 3)
    float* out = (float*)d_out;               // (B, 3, 1)

    int grid = (B_TOTAL + THREADS - 1) / THREADS;
    expm_apply_kernel<<<grid, THREADS>>>(x, c, G, out);
}

// round 4
// speedup vs baseline: 1.8026x; 1.1564x over previous
#include <cuda_runtime.h>
#include <cuda_bf16.h>

// dLDS_continuous: out[b] = expm(sum_m c[b,m] * G[m]) @ x[b]
// B = 2097152, N = 3, M = 6.
//
// Cayley-Hamilton coefficient-space expm (see round 3), now 2 batches per
// thread packed into f32x2 lanes using Blackwell packed-fp32 instructions
// (fma.rn.f32x2 / mul.rn.f32x2 / add.rn.f32x2 — PTX-only, ptxas never
// auto-packs). One scaling exponent s per pair = max of the two lanes
// (extra scaling of the smaller lane is exact and harmless).

static constexpr int B_TOTAL = 2097152;
static constexpr int THREADS = 256;
static constexpr unsigned long long SGNMASK = 0x8000000080000000ULL;

typedef unsigned long long u64;

__device__ __forceinline__ u64 pk(float a, float b) {
    u64 r; asm("mov.b64 %0, {%1,%2};" : "=l"(r) : "f"(a), "f"(b)); return r;
}
__device__ __forceinline__ void upk(u64 v, float& a, float& b) {
    asm("mov.b64 {%0,%1}, %2;" : "=f"(a), "=f"(b) : "l"(v));
}
__device__ __forceinline__ u64 f2fma(u64 a, u64 b, u64 c) {
    u64 r; asm("fma.rn.f32x2 %0, %1, %2, %3;" : "=l"(r) : "l"(a), "l"(b), "l"(c)); return r;
}
__device__ __forceinline__ u64 f2mul(u64 a, u64 b) {
    u64 r; asm("mul.rn.f32x2 %0, %1, %2;" : "=l"(r) : "l"(a), "l"(b)); return r;
}
__device__ __forceinline__ u64 f2add(u64 a, u64 b) {
    u64 r; asm("add.rn.f32x2 %0, %1, %2;" : "=l"(r) : "l"(a), "l"(b)); return r;
}
__device__ __forceinline__ u64 f2neg(u64 a) { return a ^ SGNMASK; }

__global__ void __launch_bounds__(THREADS)
expm_apply_kernel(const float* __restrict__ x,
                  const float* __restrict__ c,
                  const float* __restrict__ G,
                  float* __restrict__ out)
{
    __shared__ u64 sG[54];          // G[k] duplicated in both lanes
    int tid = threadIdx.x;
    if (tid < 54) { float g = G[tid]; sG[tid] = pk(g, g); }
    __syncthreads();

    int t = blockIdx.x * blockDim.x + tid;        // pair index, 2 batches
    // B_TOTAL/2 = 1048576 threads exactly; grid sized to match, no bound check

    // ---- load c for batches (2t, 2t+1): 12 contiguous floats = 3x float4 ----
    const float4* c4 = reinterpret_cast<const float4*>(c) + (size_t)t * 3;
    float4 q0 = c4[0];
    float4 q1 = c4[1];
    float4 q2 = c4[2];
    u64 cc[6];
    cc[0] = pk(q0.x, q1.z);
    cc[1] = pk(q0.y, q1.w);
    cc[2] = pk(q0.z, q2.x);
    cc[3] = pk(q0.w, q2.y);
    cc[4] = pk(q1.x, q2.z);
    cc[5] = pk(q1.y, q2.w);

    // ---- load x for the pair: 6 contiguous floats = 3x float2 ----
    const float2* x2 = reinterpret_cast<const float2*>(x) + (size_t)t * 3;
    float2 xa = x2[0];    // x0_0, x1_0
    float2 xb = x2[1];    // x2_0, x0_1
    float2 xc = x2[2];    // x1_1, x2_1
    u64 X0 = pk(xa.x, xb.y);
    u64 X1 = pk(xa.y, xc.x);
    u64 X2 = pk(xb.x, xc.y);

    // ---- T = sum_m c[m] * G[m] (packed, row-major 3x3) ----
    u64 A[9];
#pragma unroll
    for (int k = 0; k < 9; ++k) {
        u64 s = f2mul(cc[0], sG[k]);
#pragma unroll
        for (int m = 1; m < 6; ++m) s = f2fma(cc[m], sG[m * 9 + k], s);
        A[k] = s;
    }

    // ---- invariants ----
    u64 I1 = f2add(f2add(A[0], A[4]), A[8]);
    u64 m0 = f2fma(A[4], A[8], f2neg(f2mul(A[5], A[7])));
    u64 m1 = f2fma(A[0], A[8], f2neg(f2mul(A[2], A[6])));
    u64 m2 = f2fma(A[0], A[4], f2neg(f2mul(A[1], A[3])));
    u64 I2 = f2add(f2add(m0, m1), m2);
    u64 u1 = f2fma(A[3], A[8], f2neg(f2mul(A[5], A[6])));
    u64 u2 = f2fma(A[3], A[7], f2neg(f2mul(A[4], A[6])));
    u64 I3 = f2fma(A[0], m0, f2fma(f2neg(A[1]), u1, f2mul(A[2], u2)));

    // ---- scaling exponent: one s for the pair (max of lanes) ----
    u64 n2p = f2mul(A[0], A[0]);
#pragma unroll
    for (int k = 1; k < 9; ++k) n2p = f2fma(A[k], A[k], n2p);
    float n2lo, n2hi;
    upk(n2p, n2lo, n2hi);
    float nf = sqrtf(fmaxf(n2lo, n2hi));
    int e = (__float_as_int(nf) >> 23) - 126;     // nf < 2^e
    int s = e > 0 ? e : 0;
    if (s > 24) s = 24;
    float scf = __int_as_float((127 - s) << 23);  // exact 2^-s
    u64 sc  = pk(scf, scf);
    u64 sc2 = f2mul(sc, sc);

    // char poly of As = T*2^-s:  As^3 = c0 I + c1 As + c2 As^2
    u64 c2i = f2mul(I1, sc);
    u64 c1i = f2neg(f2mul(I2, sc2));
    u64 c0i = f2mul(I3, f2mul(sc2, sc));

    // ---- Taylor degree 9 in coefficient space ----
    u64 ONE  = pk(1.f, 1.f);
    u64 a0 = ONE, a1 = ONE, a2 = pk(0.5f, 0.5f);
    u64 p0 = 0, p1 = 0, p2 = ONE;                 // +0.0 packed = 0ull
    float tk = 0.5f;
    const float rk[7] = {1.f / 3.f, 1.f / 4.f, 1.f / 5.f, 1.f / 6.f,
                         1.f / 7.f, 1.f / 8.f, 1.f / 9.f};
#pragma unroll
    for (int k = 0; k < 7; ++k) {
        u64 np0 = f2mul(p2, c0i);
        u64 np1 = f2fma(p2, c1i, p0);
        u64 np2 = f2fma(p2, c2i, p1);
        tk *= rk[k];
        u64 tp = pk(tk, tk);
        a0 = f2fma(tp, np0, a0);
        a1 = f2fma(tp, np1, a1);
        a2 = f2fma(tp, np2, a2);
        p0 = np0; p1 = np1; p2 = np2;
    }

    // ---- As^4 reduction triple ----
    u64 d0 = f2mul(c2i, c0i);
    u64 d1 = f2fma(c2i, c1i, c0i);
    u64 d2 = f2fma(c2i, c2i, c1i);

    // ---- s squarings in coefficient space ----
    for (int it = 0; it < s; ++it) {
        u64 q01 = f2mul(a0, a1);
        u64 q02 = f2mul(a0, a2);
        u64 q12 = f2mul(a1, a2);
        u64 q22 = f2mul(a2, a2);
        u64 t12 = f2add(q12, q12);
        u64 b0 = f2fma(q22, d0, f2fma(t12, c0i, f2mul(a0, a0)));
        u64 b1 = f2fma(q22, d1, f2fma(t12, c1i, f2add(q01, q01)));
        u64 b2 = f2fma(q22, d2, f2fma(t12, c2i, f2fma(a1, a1, f2add(q02, q02))));
        a0 = b0; a1 = b1; a2 = b2;
    }

    // ---- out = a0*x + a1*(As x) + a2*(As^2 x) ----
    u64 Y0 = f2mul(sc, f2fma(A[0], X0, f2fma(A[1], X1, f2mul(A[2], X2))));
    u64 Y1 = f2mul(sc, f2fma(A[3], X0, f2fma(A[4], X1, f2mul(A[5], X2))));
    u64 Y2 = f2mul(sc, f2fma(A[6], X0, f2fma(A[7], X1, f2mul(A[8], X2))));

    u64 Z0 = f2mul(sc, f2fma(A[0], Y0, f2fma(A[1], Y1, f2mul(A[2], Y2))));
    u64 Z1 = f2mul(sc, f2fma(A[3], Y0, f2fma(A[4], Y1, f2mul(A[5], Y2))));
    u64 Z2 = f2mul(sc, f2fma(A[6], Y0, f2fma(A[7], Y1, f2mul(A[8], Y2))));

    u64 O0 = f2fma(a0, X0, f2fma(a1, Y0, f2mul(a2, Z0)));
    u64 O1 = f2fma(a0, X1, f2fma(a1, Y1, f2mul(a2, Z1)));
    u64 O2 = f2fma(a0, X2, f2fma(a1, Y2, f2mul(a2, Z2)));

    float o0l, o0h, o1l, o1h, o2l, o2h;
    upk(O0, o0l, o0h);
    upk(O1, o1l, o1h);
    upk(O2, o2l, o2h);

    float2* ob = reinterpret_cast<float2*>(out) + (size_t)t * 3;
    ob[0] = make_float2(o0l, o1l);
    ob[1] = make_float2(o2l, o0h);
    ob[2] = make_float2(o1h, o2h);
}

extern "C" void kernel_launch(void* const* d_in, const int* in_sizes, int n_in,
                              void* d_out, int out_size)
{
    const float* x = (const float*)d_in[0];   // (B, 3, 1)
    const float* c = (const float*)d_in[1];   // (B, 6)
    const float* G = (const float*)d_in[2];   // (6, 3, 3)
    float* out = (float*)d_out;               // (B, 3, 1)

    int pairs = B_TOTAL / 2;                  // 1048576
    int grid = pairs / THREADS;               // 4096
    expm_apply_kernel<<<grid, THREADS>>>(x, c, G, out);
}